// round 3
// baseline (speedup 1.0000x reference)
#include <cuda_runtime.h>
#include <math.h>
#include <float.h>

// Problem constants
#define BATCH 8192
#define NP    25      // 5x5 grid
#define NDICT 14
#define NSE   32
#define NCC   64
#define NE    256
#define NNZ   512
#define K1    400     // 16 ch * 25 pos (conv1 output)
#define K2    800     // 32 ch * 25 pos (conv2 output / linear input)

// ---------------- device scratch (no allocation allowed) ----------------
__device__ float g_embn[NDICT * NSE];
__device__ float g_PE[9 * NDICT * NCC];           // PE[k9][d][c]
__device__ float g_R1[NP * NP * NDICT * 16];      // R[p1][p2][d][o]
__device__ float g_R2[NP * NP * NDICT * 16];
__device__ float g_C1[NP * 16];                   // const for phi1 conv1
__device__ float g_zn[NNZ * NE];
__device__ float g_Wz2[NNZ * K2];                 // [z][k]
__device__ float g_cz2[NNZ];
__device__ float g_A1[BATCH * K1];                // relu1 phi1
__device__ float g_A2[BATCH * K1];                // relu1 phi2
__device__ float g_B1[(size_t)BATCH * K2];        // relu2 phi1
__device__ float g_B2[(size_t)BATCH * K2];        // relu2 phi2
__device__ float g_U1[BATCH * NE];
__device__ float g_coef[BATCH];
__device__ float g_scores[(size_t)BATCH * NNZ];
__device__ float g_G[(size_t)BATCH * NNZ];
__device__ int   g_zind[BATCH];

// ---------------- precompute kernels ----------------

// Renorm embedding rows (max_norm=1 semantics): one warp per dict row.
__global__ void k_embn(const float* __restrict__ tab) {
    int d = threadIdx.x >> 5, lane = threadIdx.x & 31;
    float v = tab[d * NSE + lane];
    float s = v * v;
    #pragma unroll
    for (int o = 16; o; o >>= 1) s += __shfl_xor_sync(0xffffffffu, s, o);
    float sc = fminf(1.0f, 1.0f / (sqrtf(s) + 1e-7f));
    g_embn[d * NSE + lane] = v * sc;
}

// L2-normalize z_vectors: one warp per row of 256.
__global__ void k_zn(const float* __restrict__ zv) {
    int row = blockIdx.x * 8 + (threadIdx.x >> 5);
    int lane = threadIdx.x & 31;
    const float* src = zv + row * NE;
    float v[8], s = 0.f;
    #pragma unroll
    for (int k = 0; k < 8; k++) { v[k] = src[lane + 32 * k]; s += v[k] * v[k]; }
    #pragma unroll
    for (int o = 16; o; o >>= 1) s += __shfl_xor_sync(0xffffffffu, s, o);
    float inv = 1.0f / sqrtf(s);
    #pragma unroll
    for (int k = 0; k < 8; k++) g_zn[row * NE + lane + 32 * k] = v[k] * inv;
}

// PE[k9][d][c] = sum_e conv_embed_w[c][e][kh][kw] * embn[d][e]
__global__ void k_PE(const float* __restrict__ cw) {
    int idx = blockIdx.x * 256 + threadIdx.x;
    if (idx >= 9 * NDICT * NCC) return;
    int c = idx % NCC;
    int d = (idx / NCC) % NDICT;
    int k9 = idx / (NCC * NDICT);
    int kh = k9 / 3, kw = k9 % 3;
    float acc = 0.f;
    #pragma unroll 8
    for (int e = 0; e < NSE; e++)
        acc += cw[((c * NSE + e) * 3 + kh) * 3 + kw] * g_embn[d * NSE + e];
    g_PE[(k9 * NDICT + d) * NCC + c] = acc;
}

// R[p1][p2][d][o]: composed (embed-conv o conv1) response, border-exact.
__global__ void k_R(const float* __restrict__ W1, float* __restrict__ R) {
    int t = blockIdx.x * blockDim.x + threadIdx.x;
    if (t >= NP * NP * NDICT * 16) return;
    int o  = t & 15;
    int d  = (t >> 4) % NDICT;
    int p2 = (t / (16 * NDICT)) % NP;
    int p1 = t / (16 * NDICT * NP);
    int h1 = p1 / 5, w1 = p1 % 5, h2 = p2 / 5, w2 = p2 % 5;
    float acc = 0.f;
    int mhlo = max(0, max(h1 - 1, h2 - 1)), mhhi = min(4, min(h1 + 1, h2 + 1));
    int mwlo = max(0, max(w1 - 1, w2 - 1)), mwhi = min(4, min(w1 + 1, w2 + 1));
    for (int mh = mhlo; mh <= mhhi; mh++)
        for (int mw = mwlo; mw <= mwhi; mw++) {
            int jh = mh - h1 + 1, jw = mw - w1 + 1;
            int kh = h2 - mh + 1, kw = w2 - mw + 1;
            const float* pe = g_PE + ((kh * 3 + kw) * NDICT + d) * NCC;
            const float* w  = W1 + o * NCC * 9 + jh * 3 + jw;
            #pragma unroll 8
            for (int c = 0; c < NCC; c++) acc += w[c * 9] * pe[c];
        }
    R[t] = acc;
}

// C1[p1][o] = b1[o] + sum_{m in N3(p1)} sum_c W1[o][c][m-p1+1] * cb[c]
__global__ void k_C1(const float* __restrict__ W1, const float* __restrict__ b1,
                     const float* __restrict__ cb) {
    int t = blockIdx.x * blockDim.x + threadIdx.x;
    if (t >= NP * 16) return;
    int o = t & 15, p1 = t >> 4;
    int h1 = p1 / 5, w1 = p1 % 5;
    float acc = b1[o];
    for (int mh = max(0, h1 - 1); mh <= min(4, h1 + 1); mh++)
        for (int mw = max(0, w1 - 1); mw <= min(4, w1 + 1); mw++) {
            int jh = mh - h1 + 1, jw = mw - w1 + 1;
            const float* w = W1 + o * NCC * 9 + jh * 3 + jw;
            #pragma unroll 8
            for (int c = 0; c < NCC; c++) acc += w[c * 9] * cb[c];
        }
    g_C1[p1 * 16 + o] = acc;
}

// Wz2[z][k] = sum_e zn[z][e] * LW2[e][k]   (scores composition, k < 800)
// grid 64 blocks (8 z each), 800 threads.
__global__ void k_Wz2(const float* __restrict__ LW2) {
    __shared__ float zr[8][NE];
    int zb = blockIdx.x * 8;
    int tid = threadIdx.x;
    for (int t = tid; t < 8 * NE; t += 800)
        zr[t >> 8][t & 255] = g_zn[(zb + (t >> 8)) * NE + (t & 255)];
    __syncthreads();
    float acc[8];
    #pragma unroll
    for (int r = 0; r < 8; r++) acc[r] = 0.f;
    for (int e = 0; e < NE; e++) {
        float lw = LW2[e * K2 + tid];
        #pragma unroll
        for (int r = 0; r < 8; r++) acc[r] += lw * zr[r][e];
    }
    #pragma unroll
    for (int r = 0; r < 8; r++) g_Wz2[(size_t)(zb + r) * K2 + tid] = acc[r];
}

// cz2[z] = sum_e lb2[e] * zn[z][e]
__global__ void k_cz2(const float* __restrict__ lb2) {
    int z = blockIdx.x * blockDim.x + threadIdx.x;
    if (z >= NNZ) return;
    float acc = 0.f;
    #pragma unroll 8
    for (int e = 0; e < NE; e++) acc += lb2[e] * g_zn[z * NE + e];
    g_cz2[z] = acc;
}

// ---------------- main pipeline ----------------

// Stage 1: relu(conv1) for both phis via LUT gather. Layout A[b][o*25+p1].
__global__ void k_stage1(const int* __restrict__ s, const int* __restrict__ sp,
                         const float* __restrict__ b1_2) {
    __shared__ int ss[NP], ssp[NP];
    int b = blockIdx.x;
    int tid = threadIdx.x;
    if (tid < NP) { ss[tid] = s[b * NP + tid]; ssp[tid] = sp[b * NP + tid]; }
    __syncthreads();
    int o = tid & 15, p1 = tid >> 4;
    int h1 = p1 / 5, w1 = p1 % 5;
    float a1 = g_C1[p1 * 16 + o];
    float a2 = b1_2[o];
    for (int h2 = max(0, h1 - 2); h2 <= min(4, h1 + 2); h2++)
        for (int w2 = max(0, w1 - 2); w2 <= min(4, w1 + 2); w2++) {
            int p2 = h2 * 5 + w2;
            int base = (p1 * NP + p2) * (NDICT * 16) + o;
            int d  = ss[p2], dp = ssp[p2];
            a1 += g_R1[base + d * 16];
            a2 += g_R2[base + dp * 16] - g_R2[base + d * 16];
        }
    g_A1[b * K1 + o * NP + p1] = fmaxf(a1, 0.f);
    g_A2[b * K1 + o * NP + p1] = fmaxf(a2, 0.f);
}

// Stage 2: B800 = relu(conv2(A400) + b2). 8 batches per block, 200 threads.
// smem acts padded 7x7, batch-innermost for float4 loads.
__global__ void __launch_bounds__(200) k_conv2(
    const float* __restrict__ A, const float* __restrict__ W2,
    const float* __restrict__ b2, float* __restrict__ Bo) {
    __shared__ float sA[16 * 7 * 7 * 8];    // [o1][h][w][b], zero-padded border
    __shared__ float sW[16 * 9 * 32];       // [o1*9+j][o2]
    int tid = threadIdx.x;
    int b0 = blockIdx.x * 8;

    // zero padded acts
    for (int i = tid; i < 16 * 49 * 8; i += 200) sA[i] = 0.f;
    // weights: sW[(o1*9+j)*32 + o2] = W2[o2*144 + o1*9 + j]
    for (int i = tid; i < 4608; i += 200) {
        int o2 = i & 31, r = i >> 5;        // r = o1*9+j
        sW[i] = W2[o2 * 144 + r];
    }
    __syncthreads();
    // fill acts: A[b][o1*25+p] -> sA[((o1*7 + h+1)*7 + w+1)*8 + b]
    for (int i = tid; i < 8 * K1; i += 200) {
        int b = i / K1, r = i % K1;
        int o1 = r / NP, p = r % NP, h = p / 5, w = p % 5;
        sA[((o1 * 7 + h + 1) * 7 + (w + 1)) * 8 + b] = A[(size_t)(b0 + b) * K1 + r];
    }
    __syncthreads();

    int pp = tid % 25, o2g = tid / 25;      // o2 = o2g*4 .. +3
    int hp = pp / 5, wp = pp % 5;
    float acc[4][8];
    #pragma unroll
    for (int q = 0; q < 4; q++)
        #pragma unroll
        for (int b = 0; b < 8; b++) acc[q][b] = 0.f;

    for (int o1 = 0; o1 < 16; o1++) {
        #pragma unroll
        for (int j = 0; j < 9; j++) {
            int kh = j / 3, kw = j % 3;
            float4 wv = *(const float4*)&sW[(o1 * 9 + j) * 32 + o2g * 4];
            int base = ((o1 * 7 + hp + kh) * 7 + (wp + kw)) * 8;
            float4 a0 = *(const float4*)&sA[base];
            float4 a1 = *(const float4*)&sA[base + 4];
            float a[8] = {a0.x, a0.y, a0.z, a0.w, a1.x, a1.y, a1.z, a1.w};
            float w[4] = {wv.x, wv.y, wv.z, wv.w};
            #pragma unroll
            for (int q = 0; q < 4; q++)
                #pragma unroll
                for (int b = 0; b < 8; b++) acc[q][b] += w[q] * a[b];
        }
    }

    #pragma unroll
    for (int q = 0; q < 4; q++) {
        int o2 = o2g * 4 + q;
        float bias = b2[o2];
        #pragma unroll
        for (int b = 0; b < 8; b++)
            Bo[(size_t)(b0 + b) * K2 + o2 * NP + pp] = fmaxf(acc[q][b] + bias, 0.f);
    }
}

// NT SGEMM: C[M,N] = rowscale[m] * (A[M,K] . B[N,K]^T + bias[n])
// 128x128 tile, BK=8, 256 threads, 8x8 micro-tile. M%128==N%128==K%8==0.
__global__ void __launch_bounds__(256) k_sgemm(
    const float* __restrict__ A, const float* __restrict__ B,
    const float* __restrict__ bias, const float* __restrict__ rowscale,
    float* __restrict__ C, int K, int N) {
    __shared__ float As[8][128];
    __shared__ float Bs[8][128];
    int tid = threadIdx.x;
    int bm = blockIdx.y * 128, bn = blockIdx.x * 128;
    int lr = tid >> 1, lk = (tid & 1) << 2;
    const float* Ap = A + (size_t)(bm + lr) * K + lk;
    const float* Bp = B + (size_t)(bn + lr) * K + lk;
    int tx = tid & 15, ty = tid >> 4;
    float acc[8][8];
    #pragma unroll
    for (int i = 0; i < 8; i++)
        #pragma unroll
        for (int j = 0; j < 8; j++) acc[i][j] = 0.f;

    for (int k0 = 0; k0 < K; k0 += 8) {
        float4 av = *(const float4*)(Ap + k0);
        float4 bv = *(const float4*)(Bp + k0);
        As[lk + 0][lr] = av.x; As[lk + 1][lr] = av.y;
        As[lk + 2][lr] = av.z; As[lk + 3][lr] = av.w;
        Bs[lk + 0][lr] = bv.x; Bs[lk + 1][lr] = bv.y;
        Bs[lk + 2][lr] = bv.z; Bs[lk + 3][lr] = bv.w;
        __syncthreads();
        #pragma unroll
        for (int kk = 0; kk < 8; kk++) {
            float4 a0 = *(const float4*)&As[kk][ty * 8];
            float4 a1 = *(const float4*)&As[kk][ty * 8 + 4];
            float4 b0 = *(const float4*)&Bs[kk][tx * 8];
            float4 b1 = *(const float4*)&Bs[kk][tx * 8 + 4];
            float a[8] = {a0.x, a0.y, a0.z, a0.w, a1.x, a1.y, a1.z, a1.w};
            float bb[8] = {b0.x, b0.y, b0.z, b0.w, b1.x, b1.y, b1.z, b1.w};
            #pragma unroll
            for (int i = 0; i < 8; i++)
                #pragma unroll
                for (int j = 0; j < 8; j++) acc[i][j] += a[i] * bb[j];
        }
        __syncthreads();
    }

    float bvals[8];
    #pragma unroll
    for (int j = 0; j < 8; j++) bvals[j] = bias ? bias[bn + tx * 8 + j] : 0.f;
    #pragma unroll
    for (int i = 0; i < 8; i++) {
        int row = bm + ty * 8 + i;
        float rs = rowscale ? rowscale[row] : 1.f;
        float4 v0, v1;
        v0.x = (acc[i][0] + bvals[0]) * rs; v0.y = (acc[i][1] + bvals[1]) * rs;
        v0.z = (acc[i][2] + bvals[2]) * rs; v0.w = (acc[i][3] + bvals[3]) * rs;
        v1.x = (acc[i][4] + bvals[4]) * rs; v1.y = (acc[i][5] + bvals[5]) * rs;
        v1.z = (acc[i][6] + bvals[6]) * rs; v1.w = (acc[i][7] + bvals[7]) * rs;
        float* cp = C + (size_t)row * N + bn + tx * 8;
        *(float4*)cp = v0;
        *(float4*)(cp + 4) = v1;
    }
}

// coef[i] = exp(scale) / (||U1_i|| + 1e-4)
__global__ void k_coef(const float* __restrict__ scale) {
    int i = blockIdx.x * 8 + (threadIdx.x >> 5);
    int lane = threadIdx.x & 31;
    const float* u = g_U1 + (size_t)i * NE;
    float s = 0.f;
    #pragma unroll
    for (int k = 0; k < 8; k++) { float v = u[lane + 32 * k]; s += v * v; }
    #pragma unroll
    for (int o = 16; o; o >>= 1) s += __shfl_xor_sync(0xffffffffu, s, o);
    if (lane == 0) g_coef[i] = expf(scale[0]) / (sqrtf(s) + 1e-4f);
}

// argmax over 512 scores per row, first-occurrence tie-break.
__global__ void k_argmax() {
    int i = blockIdx.x * 8 + (threadIdx.x >> 5);
    int lane = threadIdx.x & 31;
    const float* r = g_scores + (size_t)i * NNZ;
    float best = -FLT_MAX; int bi = 0;
    for (int z = lane; z < NNZ; z += 32) {
        float v = r[z];
        if (v > best) { best = v; bi = z; }
    }
    #pragma unroll
    for (int off = 16; off; off >>= 1) {
        float ov = __shfl_down_sync(0xffffffffu, best, off);
        int   oi = __shfl_down_sync(0xffffffffu, bi, off);
        if (ov > best || (ov == best && oi < bi)) { best = ov; bi = oi; }
    }
    if (lane == 0) g_zind[i] = bi;
}

// out[i][j] = G[i][zind[j]]  (256 MB coalesced write)
__global__ void k_out(float* __restrict__ out) {
    __shared__ float row[NNZ];
    __shared__ int zj[4096];
    int i = blockIdx.y;
    int jb = blockIdx.x * 4096;
    for (int t = threadIdx.x; t < NNZ; t += 256) row[t] = g_G[(size_t)i * NNZ + t];
    for (int t = threadIdx.x; t < 4096; t += 256) zj[t] = g_zind[jb + t];
    __syncthreads();
    float* op = out + (size_t)i * BATCH + jb;
    #pragma unroll
    for (int k = 0; k < 16; k++) {
        int j = k * 256 + threadIdx.x;
        op[j] = row[zj[j]];
    }
}

// ---------------- launcher ----------------
extern "C" void kernel_launch(void* const* d_in, const int* in_sizes, int n_in,
                              void* d_out, int out_size) {
    const int*   s     = (const int*)d_in[0];
    const int*   sp    = (const int*)d_in[1];
    const float* tab   = (const float*)d_in[2];
    const float* cw    = (const float*)d_in[3];
    const float* cb    = (const float*)d_in[4];
    const float* w1a   = (const float*)d_in[5];
    const float* b1a   = (const float*)d_in[6];
    const float* w2a   = (const float*)d_in[7];
    const float* b2a   = (const float*)d_in[8];
    const float* lwa   = (const float*)d_in[9];
    const float* lba   = (const float*)d_in[10];
    const float* w1b   = (const float*)d_in[11];
    const float* b1b   = (const float*)d_in[12];
    const float* w2b   = (const float*)d_in[13];
    const float* b2b   = (const float*)d_in[14];
    const float* lwb   = (const float*)d_in[15];
    const float* lbb   = (const float*)d_in[16];
    const float* zv    = (const float*)d_in[17];
    const float* scale = (const float*)d_in[18];
    float* out = (float*)d_out;

    float *pR1, *pR2, *pA1, *pA2, *pB1, *pB2, *pU1, *pzn,
          *pWz2, *pcz2, *pscores, *pG, *pcoef;
    cudaGetSymbolAddress((void**)&pR1, g_R1);
    cudaGetSymbolAddress((void**)&pR2, g_R2);
    cudaGetSymbolAddress((void**)&pA1, g_A1);
    cudaGetSymbolAddress((void**)&pA2, g_A2);
    cudaGetSymbolAddress((void**)&pB1, g_B1);
    cudaGetSymbolAddress((void**)&pB2, g_B2);
    cudaGetSymbolAddress((void**)&pU1, g_U1);
    cudaGetSymbolAddress((void**)&pzn, g_zn);
    cudaGetSymbolAddress((void**)&pWz2, g_Wz2);
    cudaGetSymbolAddress((void**)&pcz2, g_cz2);
    cudaGetSymbolAddress((void**)&pscores, g_scores);
    cudaGetSymbolAddress((void**)&pG, g_G);
    cudaGetSymbolAddress((void**)&pcoef, g_coef);

    // Precompute (every call; deterministic)
    k_embn<<<1, 448>>>(tab);
    k_zn<<<64, 256>>>(zv);
    k_PE<<<32, 256>>>(cw);
    k_R<<<547, 256>>>(w1a, pR1);
    k_R<<<547, 256>>>(w1b, pR2);
    k_C1<<<2, 256>>>(w1a, b1a, cb);
    k_Wz2<<<64, 800>>>(lwb);
    k_cz2<<<2, 256>>>(lbb);

    // Main pipeline
    k_stage1<<<BATCH, 400>>>(s, sp, b1b);

    k_conv2<<<BATCH / 8, 200>>>(pA1, w2a, b2a, pB1);
    k_conv2<<<BATCH / 8, 200>>>(pA2, w2b, b2b, pB2);

    dim3 gU(NE / 128, BATCH / 128);      // 2 x 64
    k_sgemm<<<gU, 256>>>(pB1, lwa, lba, nullptr, pU1, K2, NE);
    k_coef<<<1024, 256>>>(scale);

    dim3 gZ(NNZ / 128, BATCH / 128);     // 4 x 64
    k_sgemm<<<gZ, 256>>>(pB2, pWz2, pcz2, nullptr, pscores, K2, NNZ);
    k_argmax<<<1024, 256>>>();

    k_sgemm<<<gZ, 256>>>(pU1, pzn, nullptr, pcoef, pG, NE, NNZ);

    k_out<<<dim3(2, BATCH), 256>>>(out);
}

// round 8
// speedup vs baseline: 1.2641x; 1.2641x over previous
#include <cuda_runtime.h>
#include <math.h>
#include <float.h>

// Problem constants
#define BATCH 8192
#define NP    25      // 5x5 grid
#define NDICT 14
#define NSE   32
#define NCC   64
#define NE    256
#define NNZ   512
#define K1    400     // 16 ch * 25 pos (conv1 output)
#define K2    800     // 32 ch * 25 pos (conv2 output / linear input)

// ---------------- device scratch (no allocation allowed) ----------------
__device__ float g_embn[NDICT * NSE];
__device__ float g_PE[9 * NDICT * NCC];           // PE[k9][d][c]
__device__ float g_R1[NP * NP * NDICT * 16];      // R[p1][p2][d][o]
__device__ float g_R2[NP * NP * NDICT * 16];
__device__ float g_C1[NP * 16];                   // const for phi1 conv1 [p1*16+o]
__device__ float g_zn[NNZ * NE];
__device__ float g_Wz2[NNZ * K2];                 // [z][k]
__device__ float g_cz2[NNZ];
__device__ float g_A1[BATCH * K1];                // relu1 phi1, layout [b][p*16+o]
__device__ float g_A2[BATCH * K1];                // relu1 phi2
__device__ float g_B1[(size_t)BATCH * K2];        // relu2 phi1, layout [b][o2*25+p]
__device__ float g_B2[(size_t)BATCH * K2];        // relu2 phi2
__device__ float g_U1[BATCH * NE];
__device__ float g_coef[BATCH];
__device__ float g_scores[(size_t)BATCH * NNZ];
__device__ float g_G[(size_t)BATCH * NNZ];
__device__ int   g_zind[BATCH];

// ---------------- precompute kernels ----------------

// Renorm embedding rows (max_norm=1 semantics): one warp per dict row.
__global__ void k_embn(const float* __restrict__ tab) {
    int d = threadIdx.x >> 5, lane = threadIdx.x & 31;
    float v = tab[d * NSE + lane];
    float s = v * v;
    #pragma unroll
    for (int o = 16; o; o >>= 1) s += __shfl_xor_sync(0xffffffffu, s, o);
    float sc = fminf(1.0f, 1.0f / (sqrtf(s) + 1e-7f));
    g_embn[d * NSE + lane] = v * sc;
}

// L2-normalize z_vectors: one warp per row of 256.
__global__ void k_zn(const float* __restrict__ zv) {
    int row = blockIdx.x * 8 + (threadIdx.x >> 5);
    int lane = threadIdx.x & 31;
    const float* src = zv + row * NE;
    float v[8], s = 0.f;
    #pragma unroll
    for (int k = 0; k < 8; k++) { v[k] = src[lane + 32 * k]; s += v[k] * v[k]; }
    #pragma unroll
    for (int o = 16; o; o >>= 1) s += __shfl_xor_sync(0xffffffffu, s, o);
    float inv = 1.0f / sqrtf(s);
    #pragma unroll
    for (int k = 0; k < 8; k++) g_zn[row * NE + lane + 32 * k] = v[k] * inv;
}

// PE[k9][d][c] = sum_e conv_embed_w[c][e][kh][kw] * embn[d][e]
__global__ void k_PE(const float* __restrict__ cw) {
    int idx = blockIdx.x * 256 + threadIdx.x;
    if (idx >= 9 * NDICT * NCC) return;
    int c = idx % NCC;
    int d = (idx / NCC) % NDICT;
    int k9 = idx / (NCC * NDICT);
    int kh = k9 / 3, kw = k9 % 3;
    float acc = 0.f;
    #pragma unroll 8
    for (int e = 0; e < NSE; e++)
        acc += cw[((c * NSE + e) * 3 + kh) * 3 + kw] * g_embn[d * NSE + e];
    g_PE[(k9 * NDICT + d) * NCC + c] = acc;
}

// R[p1][p2][d][o]: composed (embed-conv o conv1) response, border-exact.
// One block per (p1,d); W1 + PE-slice staged in smem.
__global__ void __launch_bounds__(400) k_R(const float* __restrict__ W1,
                                           float* __restrict__ R) {
    __shared__ float sW[9216];     // [(c*9+j)*16 + o]
    __shared__ float sPE[9 * 64];  // [k9*64 + c]
    int p1 = blockIdx.x / NDICT, d = blockIdx.x % NDICT;
    int tid = threadIdx.x;
    for (int i = tid; i < 9216; i += 400) {
        int o = i / 576, r = i % 576;          // r = c*9+j
        sW[r * 16 + o] = W1[i];
    }
    for (int i = tid; i < 576; i += 400)
        sPE[i] = g_PE[((i / 64) * NDICT + d) * NCC + (i % 64)];
    __syncthreads();

    int p2 = tid >> 4, o = tid & 15;           // p2 < 25
    int h1 = p1 / 5, w1 = p1 % 5, h2 = p2 / 5, w2 = p2 % 5;
    float acc = 0.f;
    int mhlo = max(0, max(h1, h2) - 1), mhhi = min(4, min(h1, h2) + 1);
    int mwlo = max(0, max(w1, w2) - 1), mwhi = min(4, min(w1, w2) + 1);
    for (int mh = mhlo; mh <= mhhi; mh++)
        for (int mw = mwlo; mw <= mwhi; mw++) {
            int j  = (mh - h1 + 1) * 3 + (mw - w1 + 1);
            int k9 = (h2 - mh + 1) * 3 + (w2 - mw + 1);
            const float* pe = sPE + k9 * 64;
            const float* w  = sW + j * 16 + o;
            #pragma unroll
            for (int c = 0; c < 64; c++) acc += w[c * 144] * pe[c];
        }
    R[((p1 * NP + p2) * NDICT + d) * 16 + o] = acc;
}

// C1[p1*16+o] = b1[o] + sum_{m in N3(p1)} sum_c W1[o][c][m-p1+1] * cb[c]
__global__ void k_C1(const float* __restrict__ W1, const float* __restrict__ b1,
                     const float* __restrict__ cb) {
    int t = blockIdx.x * blockDim.x + threadIdx.x;
    if (t >= NP * 16) return;
    int o = t & 15, p1 = t >> 4;
    int h1 = p1 / 5, w1 = p1 % 5;
    float acc = b1[o];
    for (int mh = max(0, h1 - 1); mh <= min(4, h1 + 1); mh++)
        for (int mw = max(0, w1 - 1); mw <= min(4, w1 + 1); mw++) {
            int jh = mh - h1 + 1, jw = mw - w1 + 1;
            const float* w = W1 + o * NCC * 9 + jh * 3 + jw;
            #pragma unroll 8
            for (int c = 0; c < NCC; c++) acc += w[c * 9] * cb[c];
        }
    g_C1[p1 * 16 + o] = acc;
}

// Wz2[z][k] = sum_e zn[z][e] * LW2[e][k]
__global__ void k_Wz2(const float* __restrict__ LW2) {
    __shared__ float zr[8][NE];
    int zb = blockIdx.x * 8;
    int tid = threadIdx.x;
    for (int t = tid; t < 8 * NE; t += 800)
        zr[t >> 8][t & 255] = g_zn[(zb + (t >> 8)) * NE + (t & 255)];
    __syncthreads();
    float acc[8];
    #pragma unroll
    for (int r = 0; r < 8; r++) acc[r] = 0.f;
    for (int e = 0; e < NE; e++) {
        float lw = LW2[e * K2 + tid];
        #pragma unroll
        for (int r = 0; r < 8; r++) acc[r] += lw * zr[r][e];
    }
    #pragma unroll
    for (int r = 0; r < 8; r++) g_Wz2[(size_t)(zb + r) * K2 + tid] = acc[r];
}

// cz2[z] = sum_e lb2[e] * zn[z][e]
__global__ void k_cz2(const float* __restrict__ lb2) {
    int z = blockIdx.x * blockDim.x + threadIdx.x;
    if (z >= NNZ) return;
    float acc = 0.f;
    #pragma unroll 8
    for (int e = 0; e < NE; e++) acc += lb2[e] * g_zn[z * NE + e];
    g_cz2[z] = acc;
}

// ---------------- main pipeline ----------------

// Stage 1: relu(conv1) via LUT gather, float4 per thread, 8 batches/block.
// Output layout A[b][p1*16+o].
__global__ void __launch_bounds__(800) k_stage1(const int* __restrict__ s,
                                                const int* __restrict__ sp,
                                                const float* __restrict__ b1_2) {
    __shared__ int ss[8][NP], ssp[8][NP];
    int b0 = blockIdx.x * 8;
    int tid = threadIdx.x;
    if (tid < 200) {
        int b = tid / NP, p = tid % NP;
        ss[b][p]  = s[(b0 + b) * NP + p];
        ssp[b][p] = sp[(b0 + b) * NP + p];
    }
    __syncthreads();
    int bl = tid / 100, rem = tid % 100;
    int p1 = rem >> 2, og = rem & 3;
    int h1 = p1 / 5, w1 = p1 % 5;
    float4 a1 = *(const float4*)&g_C1[p1 * 16 + og * 4];
    float4 a2 = *(const float4*)&b1_2[og * 4];
    for (int h2 = max(0, h1 - 2); h2 <= min(4, h1 + 2); h2++)
        for (int w2 = max(0, w1 - 2); w2 <= min(4, w1 + 2); w2++) {
            int p2 = h2 * 5 + w2;
            int base = (p1 * NP + p2) * (NDICT * 16) + og * 4;
            int d = ss[bl][p2], dp = ssp[bl][p2];
            float4 r1  = *(const float4*)&g_R1[base + d * 16];
            float4 r2a = *(const float4*)&g_R2[base + dp * 16];
            float4 r2b = *(const float4*)&g_R2[base + d * 16];
            a1.x += r1.x; a1.y += r1.y; a1.z += r1.z; a1.w += r1.w;
            a2.x += r2a.x - r2b.x; a2.y += r2a.y - r2b.y;
            a2.z += r2a.z - r2b.z; a2.w += r2a.w - r2b.w;
        }
    float4 o1 = make_float4(fmaxf(a1.x, 0.f), fmaxf(a1.y, 0.f),
                            fmaxf(a1.z, 0.f), fmaxf(a1.w, 0.f));
    float4 o2 = make_float4(fmaxf(a2.x, 0.f), fmaxf(a2.y, 0.f),
                            fmaxf(a2.z, 0.f), fmaxf(a2.w, 0.f));
    size_t off = (size_t)(b0 + bl) * K1 + p1 * 16 + og * 4;
    *(float4*)&g_A1[off] = o1;
    *(float4*)&g_A2[off] = o2;
}

// Stage 2: B800 = relu(conv2(A400) + b2). 8 batches/block, 200 threads.
// A layout [b][p*16+o1]; smem acts [o1][h][w][12] (pad 12 vs 8 for banks).
#define CPAD 12
__global__ void __launch_bounds__(200) k_conv2(
    const float* __restrict__ A, const float* __restrict__ W2,
    const float* __restrict__ b2, float* __restrict__ Bo) {
    __shared__ float sA[16 * 7 * 7 * CPAD];
    __shared__ float sW[16 * 9 * 32];       // [o1*9+j][o2]
    int tid = threadIdx.x;
    int b0 = blockIdx.x * 8;

    for (int i = tid; i < 16 * 49 * CPAD; i += 200) sA[i] = 0.f;
    for (int i = tid; i < 4608; i += 200) {
        int o2 = i & 31, r = i >> 5;        // r = o1*9+j
        sW[i] = W2[o2 * 144 + r];
    }
    __syncthreads();
    // A[b][p*16+o1] -> sA[((o1*7 + h+1)*7 + w+1)*CPAD + b]
    for (int i = tid; i < 8 * K1; i += 200) {
        int b = i / K1, r = i % K1;
        int p = r >> 4, o1 = r & 15, h = p / 5, w = p % 5;
        sA[((o1 * 7 + h + 1) * 7 + (w + 1)) * CPAD + b] = A[(size_t)(b0 + b) * K1 + r];
    }
    __syncthreads();

    int pp = tid % 25, o2g = tid / 25;      // o2 = o2g*4 .. +3
    int hp = pp / 5, wp = pp % 5;
    float acc[4][8];
    #pragma unroll
    for (int q = 0; q < 4; q++)
        #pragma unroll
        for (int b = 0; b < 8; b++) acc[q][b] = 0.f;

    for (int o1 = 0; o1 < 16; o1++) {
        #pragma unroll
        for (int j = 0; j < 9; j++) {
            int kh = j / 3, kw = j % 3;
            float4 wv = *(const float4*)&sW[(o1 * 9 + j) * 32 + o2g * 4];
            int base = ((o1 * 7 + hp + kh) * 7 + (wp + kw)) * CPAD;
            float4 a0 = *(const float4*)&sA[base];
            float4 a1 = *(const float4*)&sA[base + 4];
            float a[8] = {a0.x, a0.y, a0.z, a0.w, a1.x, a1.y, a1.z, a1.w};
            float w[4] = {wv.x, wv.y, wv.z, wv.w};
            #pragma unroll
            for (int q = 0; q < 4; q++)
                #pragma unroll
                for (int b = 0; b < 8; b++) acc[q][b] += w[q] * a[b];
        }
    }

    #pragma unroll
    for (int q = 0; q < 4; q++) {
        int o2 = o2g * 4 + q;
        float bias = b2[o2];
        #pragma unroll
        for (int b = 0; b < 8; b++)
            Bo[(size_t)(b0 + b) * K2 + o2 * NP + pp] = fmaxf(acc[q][b] + bias, 0.f);
    }
}

// NT SGEMM: C[M,N] = rowscale[m] * (A[M,K] . B[N,K]^T + bias[n])
// 128x128 tile, BK=16, double-buffered smem, 256 threads, 8x8 micro-tile.
#define BK 16
__global__ void __launch_bounds__(256) k_sgemm(
    const float* __restrict__ A, const float* __restrict__ B,
    const float* __restrict__ bias, const float* __restrict__ rowscale,
    float* __restrict__ C, int K, int N) {
    __shared__ float As[2][BK][128];
    __shared__ float Bs[2][BK][128];
    int tid = threadIdx.x;
    int bm = blockIdx.y * 128, bn = blockIdx.x * 128;
    int lr = tid >> 2, lc = (tid & 3) << 2;   // rows lr, lr+64; cols lc..lc+3
    const float* Ap = A + (size_t)(bm + lr) * K + lc;
    const float* Bp = B + (size_t)(bn + lr) * K + lc;
    size_t rowoff = (size_t)64 * K;
    int tx = tid & 15, ty = tid >> 4;
    float acc[8][8];
    #pragma unroll
    for (int i = 0; i < 8; i++)
        #pragma unroll
        for (int j = 0; j < 8; j++) acc[i][j] = 0.f;

    int nT = K / BK;
    float4 a0v = *(const float4*)(Ap);
    float4 a1v = *(const float4*)(Ap + rowoff);
    float4 b0v = *(const float4*)(Bp);
    float4 b1v = *(const float4*)(Bp + rowoff);
    #pragma unroll
    for (int q = 0; q < 4; q++) {
        As[0][lc + q][lr]      = ((const float*)&a0v)[q];
        As[0][lc + q][lr + 64] = ((const float*)&a1v)[q];
        Bs[0][lc + q][lr]      = ((const float*)&b0v)[q];
        Bs[0][lc + q][lr + 64] = ((const float*)&b1v)[q];
    }
    __syncthreads();

    int cur = 0;
    for (int t = 0; t < nT; t++) {
        float4 na0, na1, nb0, nb1;
        if (t + 1 < nT) {
            const float* Ap2 = Ap + (t + 1) * BK;
            const float* Bp2 = Bp + (t + 1) * BK;
            na0 = *(const float4*)(Ap2);
            na1 = *(const float4*)(Ap2 + rowoff);
            nb0 = *(const float4*)(Bp2);
            nb1 = *(const float4*)(Bp2 + rowoff);
        }
        #pragma unroll
        for (int kk = 0; kk < BK; kk++) {
            float4 x0 = *(const float4*)&As[cur][kk][ty * 8];
            float4 x1 = *(const float4*)&As[cur][kk][ty * 8 + 4];
            float4 y0 = *(const float4*)&Bs[cur][kk][tx * 8];
            float4 y1 = *(const float4*)&Bs[cur][kk][tx * 8 + 4];
            float a[8] = {x0.x, x0.y, x0.z, x0.w, x1.x, x1.y, x1.z, x1.w};
            float bb[8] = {y0.x, y0.y, y0.z, y0.w, y1.x, y1.y, y1.z, y1.w};
            #pragma unroll
            for (int i = 0; i < 8; i++)
                #pragma unroll
                for (int j = 0; j < 8; j++) acc[i][j] += a[i] * bb[j];
        }
        if (t + 1 < nT) {
            int nxt = cur ^ 1;
            #pragma unroll
            for (int q = 0; q < 4; q++) {
                As[nxt][lc + q][lr]      = ((const float*)&na0)[q];
                As[nxt][lc + q][lr + 64] = ((const float*)&na1)[q];
                Bs[nxt][lc + q][lr]      = ((const float*)&nb0)[q];
                Bs[nxt][lc + q][lr + 64] = ((const float*)&nb1)[q];
            }
            __syncthreads();
            cur = nxt;
        }
    }

    float bvals[8];
    #pragma unroll
    for (int j = 0; j < 8; j++) bvals[j] = bias ? bias[bn + tx * 8 + j] : 0.f;
    #pragma unroll
    for (int i = 0; i < 8; i++) {
        int row = bm + ty * 8 + i;
        float rs = rowscale ? rowscale[row] : 1.f;
        float4 v0, v1;
        v0.x = (acc[i][0] + bvals[0]) * rs; v0.y = (acc[i][1] + bvals[1]) * rs;
        v0.z = (acc[i][2] + bvals[2]) * rs; v0.w = (acc[i][3] + bvals[3]) * rs;
        v1.x = (acc[i][4] + bvals[4]) * rs; v1.y = (acc[i][5] + bvals[5]) * rs;
        v1.z = (acc[i][6] + bvals[6]) * rs; v1.w = (acc[i][7] + bvals[7]) * rs;
        float* cp = C + (size_t)row * N + bn + tx * 8;
        *(float4*)cp = v0;
        *(float4*)(cp + 4) = v1;
    }
}

// coef[i] = exp(scale) / (||U1_i|| + 1e-4)
__global__ void k_coef(const float* __restrict__ scale) {
    int i = blockIdx.x * 8 + (threadIdx.x >> 5);
    int lane = threadIdx.x & 31;
    const float* u = g_U1 + (size_t)i * NE;
    float s = 0.f;
    #pragma unroll
    for (int k = 0; k < 8; k++) { float v = u[lane + 32 * k]; s += v * v; }
    #pragma unroll
    for (int o = 16; o; o >>= 1) s += __shfl_xor_sync(0xffffffffu, s, o);
    if (lane == 0) g_coef[i] = expf(scale[0]) / (sqrtf(s) + 1e-4f);
}

// argmax over 512 scores per row, first-occurrence tie-break.
__global__ void k_argmax() {
    int i = blockIdx.x * 8 + (threadIdx.x >> 5);
    int lane = threadIdx.x & 31;
    const float* r = g_scores + (size_t)i * NNZ;
    float best = -FLT_MAX; int bi = 0;
    for (int z = lane; z < NNZ; z += 32) {
        float v = r[z];
        if (v > best) { best = v; bi = z; }
    }
    #pragma unroll
    for (int off = 16; off; off >>= 1) {
        float ov = __shfl_down_sync(0xffffffffu, best, off);
        int   oi = __shfl_down_sync(0xffffffffu, bi, off);
        if (ov > best || (ov == best && oi < bi)) { best = ov; bi = oi; }
    }
    if (lane == 0) g_zind[i] = bi;
}

// out[i][j] = G[i][zind[j]]  (256 MB coalesced write)
__global__ void k_out(float* __restrict__ out) {
    __shared__ float row[NNZ];
    __shared__ int zj[4096];
    int i = blockIdx.y;
    int jb = blockIdx.x * 4096;
    for (int t = threadIdx.x; t < NNZ; t += 256) row[t] = g_G[(size_t)i * NNZ + t];
    for (int t = threadIdx.x; t < 4096; t += 256) zj[t] = g_zind[jb + t];
    __syncthreads();
    float* op = out + (size_t)i * BATCH + jb;
    #pragma unroll
    for (int k = 0; k < 16; k++) {
        int j = k * 256 + threadIdx.x;
        op[j] = row[zj[j]];
    }
}

// ---------------- launcher ----------------
extern "C" void kernel_launch(void* const* d_in, const int* in_sizes, int n_in,
                              void* d_out, int out_size) {
    const int*   s     = (const int*)d_in[0];
    const int*   sp    = (const int*)d_in[1];
    const float* tab   = (const float*)d_in[2];
    const float* cw    = (const float*)d_in[3];
    const float* cb    = (const float*)d_in[4];
    const float* w1a   = (const float*)d_in[5];
    const float* b1a   = (const float*)d_in[6];
    const float* w2a   = (const float*)d_in[7];
    const float* b2a   = (const float*)d_in[8];
    const float* lwa   = (const float*)d_in[9];
    const float* lba   = (const float*)d_in[10];
    const float* w1b   = (const float*)d_in[11];
    const float* b1b   = (const float*)d_in[12];
    const float* w2b   = (const float*)d_in[13];
    const float* b2b   = (const float*)d_in[14];
    const float* lwb   = (const float*)d_in[15];
    const float* lbb   = (const float*)d_in[16];
    const float* zv    = (const float*)d_in[17];
    const float* scale = (const float*)d_in[18];
    float* out = (float*)d_out;

    float *pR1, *pR2, *pA1, *pA2, *pB1, *pB2, *pU1, *pzn,
          *pWz2, *pcz2, *pscores, *pG, *pcoef;
    cudaGetSymbolAddress((void**)&pR1, g_R1);
    cudaGetSymbolAddress((void**)&pR2, g_R2);
    cudaGetSymbolAddress((void**)&pA1, g_A1);
    cudaGetSymbolAddress((void**)&pA2, g_A2);
    cudaGetSymbolAddress((void**)&pB1, g_B1);
    cudaGetSymbolAddress((void**)&pB2, g_B2);
    cudaGetSymbolAddress((void**)&pU1, g_U1);
    cudaGetSymbolAddress((void**)&pzn, g_zn);
    cudaGetSymbolAddress((void**)&pWz2, g_Wz2);
    cudaGetSymbolAddress((void**)&pcz2, g_cz2);
    cudaGetSymbolAddress((void**)&pscores, g_scores);
    cudaGetSymbolAddress((void**)&pG, g_G);
    cudaGetSymbolAddress((void**)&pcoef, g_coef);

    // Precompute (every call; deterministic)
    k_embn<<<1, 448>>>(tab);
    k_zn<<<64, 256>>>(zv);
    k_PE<<<32, 256>>>(cw);
    k_R<<<NP * NDICT, 400>>>(w1a, pR1);
    k_R<<<NP * NDICT, 400>>>(w1b, pR2);
    k_C1<<<2, 256>>>(w1a, b1a, cb);
    k_Wz2<<<64, 800>>>(lwb);
    k_cz2<<<2, 256>>>(lbb);

    // Main pipeline
    k_stage1<<<BATCH / 8, 800>>>(s, sp, b1b);

    k_conv2<<<BATCH / 8, 200>>>(pA1, w2a, b2a, pB1);
    k_conv2<<<BATCH / 8, 200>>>(pA2, w2b, b2b, pB2);

    dim3 gU(NE / 128, BATCH / 128);      // 2 x 64
    k_sgemm<<<gU, 256>>>(pB1, lwa, lba, nullptr, pU1, K2, NE);
    k_coef<<<1024, 256>>>(scale);

    dim3 gZ(NNZ / 128, BATCH / 128);     // 4 x 64
    k_sgemm<<<gZ, 256>>>(pB2, pWz2, pcz2, nullptr, pscores, K2, NNZ);
    k_argmax<<<1024, 256>>>();

    k_sgemm<<<gZ, 256>>>(pU1, pzn, nullptr, pcoef, pG, NE, NNZ);

    k_out<<<dim3(2, BATCH), 256>>>(out);
}

// round 9
// speedup vs baseline: 1.6135x; 1.2764x over previous
#include <cuda_runtime.h>
#include <math.h>
#include <float.h>

// Problem constants
#define BATCH 8192
#define NP    25      // 5x5 grid
#define NDICT 14
#define NSE   32
#define NCC   64
#define NE    256
#define NNZ   512
#define K1    400     // 16 ch * 25 pos (conv1 output)
#define K2    800     // 32 ch * 25 pos (conv2 output / linear input)

// ---------------- device scratch (no allocation allowed) ----------------
__device__ float g_embn[NDICT * NSE];
__device__ float g_PE[9 * NDICT * NCC];           // PE[k9][d][c]
__device__ float g_R1[NP * NP * NDICT * 16];      // R[p1][p2][d][o]
__device__ float g_R2[NP * NP * NDICT * 16];
__device__ float g_C1[NP * 16];                   // const for phi1 conv1 [p1*16+o]
__device__ float g_zn[NNZ * NE];
__device__ float g_A1[BATCH * K1];                // relu1 phi1, layout [b][p*16+o]
__device__ float g_A2[BATCH * K1];                // relu1 phi2
__device__ float g_B1[(size_t)BATCH * K2];        // relu2 phi1, layout [b][o2*25+p]
__device__ float g_B2[(size_t)BATCH * K2];        // relu2 phi2
__device__ float g_U1[BATCH * NE];
__device__ float g_E2[BATCH * NE];
__device__ float g_coef[BATCH];
__device__ float g_scores[(size_t)BATCH * NNZ];
__device__ float g_G[(size_t)BATCH * NNZ];
__device__ int   g_zind[BATCH];

// ---------------- precompute kernels ----------------

// Renorm embedding rows (max_norm=1 semantics): one warp per dict row.
__global__ void k_embn(const float* __restrict__ tab) {
    int d = threadIdx.x >> 5, lane = threadIdx.x & 31;
    float v = tab[d * NSE + lane];
    float s = v * v;
    #pragma unroll
    for (int o = 16; o; o >>= 1) s += __shfl_xor_sync(0xffffffffu, s, o);
    float sc = fminf(1.0f, 1.0f / (sqrtf(s) + 1e-7f));
    g_embn[d * NSE + lane] = v * sc;
}

// L2-normalize z_vectors: one warp per row of 256.
__global__ void k_zn(const float* __restrict__ zv) {
    int row = blockIdx.x * 8 + (threadIdx.x >> 5);
    int lane = threadIdx.x & 31;
    const float* src = zv + row * NE;
    float v[8], s = 0.f;
    #pragma unroll
    for (int k = 0; k < 8; k++) { v[k] = src[lane + 32 * k]; s += v[k] * v[k]; }
    #pragma unroll
    for (int o = 16; o; o >>= 1) s += __shfl_xor_sync(0xffffffffu, s, o);
    float inv = 1.0f / sqrtf(s);
    #pragma unroll
    for (int k = 0; k < 8; k++) g_zn[row * NE + lane + 32 * k] = v[k] * inv;
}

// PE[k9][d][c] = sum_e conv_embed_w[c][e][kh][kw] * embn[d][e]
__global__ void k_PE(const float* __restrict__ cw) {
    int idx = blockIdx.x * 256 + threadIdx.x;
    if (idx >= 9 * NDICT * NCC) return;
    int c = idx % NCC;
    int d = (idx / NCC) % NDICT;
    int k9 = idx / (NCC * NDICT);
    int kh = k9 / 3, kw = k9 % 3;
    float acc = 0.f;
    #pragma unroll 8
    for (int e = 0; e < NSE; e++)
        acc += cw[((c * NSE + e) * 3 + kh) * 3 + kw] * g_embn[d * NSE + e];
    g_PE[(k9 * NDICT + d) * NCC + c] = acc;
}

// R[p1][p2][d][o]: composed (embed-conv o conv1) response, border-exact.
__global__ void __launch_bounds__(400) k_R(const float* __restrict__ W1,
                                           float* __restrict__ R) {
    __shared__ float sW[9216];     // [(c*9+j)*16 + o]
    __shared__ float sPE[9 * 64];  // [k9*64 + c]
    int p1 = blockIdx.x / NDICT, d = blockIdx.x % NDICT;
    int tid = threadIdx.x;
    for (int i = tid; i < 9216; i += 400) {
        int o = i / 576, r = i % 576;          // r = c*9+j
        sW[r * 16 + o] = W1[i];
    }
    for (int i = tid; i < 576; i += 400)
        sPE[i] = g_PE[((i / 64) * NDICT + d) * NCC + (i % 64)];
    __syncthreads();

    int p2 = tid >> 4, o = tid & 15;           // p2 < 25
    int h1 = p1 / 5, w1 = p1 % 5, h2 = p2 / 5, w2 = p2 % 5;
    float acc = 0.f;
    int mhlo = max(0, max(h1, h2) - 1), mhhi = min(4, min(h1, h2) + 1);
    int mwlo = max(0, max(w1, w2) - 1), mwhi = min(4, min(w1, w2) + 1);
    for (int mh = mhlo; mh <= mhhi; mh++)
        for (int mw = mwlo; mw <= mwhi; mw++) {
            int j  = (mh - h1 + 1) * 3 + (mw - w1 + 1);
            int k9 = (h2 - mh + 1) * 3 + (w2 - mw + 1);
            const float* pe = sPE + k9 * 64;
            const float* w  = sW + j * 16 + o;
            #pragma unroll
            for (int c = 0; c < 64; c++) acc += w[c * 144] * pe[c];
        }
    R[((p1 * NP + p2) * NDICT + d) * 16 + o] = acc;
}

// C1[p1*16+o] = b1[o] + sum_{m in N3(p1)} sum_c W1[o][c][m-p1+1] * cb[c]
__global__ void k_C1(const float* __restrict__ W1, const float* __restrict__ b1,
                     const float* __restrict__ cb) {
    int t = blockIdx.x * blockDim.x + threadIdx.x;
    if (t >= NP * 16) return;
    int o = t & 15, p1 = t >> 4;
    int h1 = p1 / 5, w1 = p1 % 5;
    float acc = b1[o];
    for (int mh = max(0, h1 - 1); mh <= min(4, h1 + 1); mh++)
        for (int mw = max(0, w1 - 1); mw <= min(4, w1 + 1); mw++) {
            int jh = mh - h1 + 1, jw = mw - w1 + 1;
            const float* w = W1 + o * NCC * 9 + jh * 3 + jw;
            #pragma unroll 8
            for (int c = 0; c < NCC; c++) acc += w[c * 9] * cb[c];
        }
    g_C1[p1 * 16 + o] = acc;
}

// ---------------- main pipeline ----------------

// Stage 1: relu(conv1) via LUT gather, float4 per thread, 8 batches/block.
__global__ void __launch_bounds__(800) k_stage1(const int* __restrict__ s,
                                                const int* __restrict__ sp,
                                                const float* __restrict__ b1_2) {
    __shared__ int ss[8][NP], ssp[8][NP];
    int b0 = blockIdx.x * 8;
    int tid = threadIdx.x;
    if (tid < 200) {
        int b = tid / NP, p = tid % NP;
        ss[b][p]  = s[(b0 + b) * NP + p];
        ssp[b][p] = sp[(b0 + b) * NP + p];
    }
    __syncthreads();
    int bl = tid / 100, rem = tid % 100;
    int p1 = rem >> 2, og = rem & 3;
    int h1 = p1 / 5, w1 = p1 % 5;
    float4 a1 = *(const float4*)&g_C1[p1 * 16 + og * 4];
    float4 a2 = *(const float4*)&b1_2[og * 4];
    for (int h2 = max(0, h1 - 2); h2 <= min(4, h1 + 2); h2++)
        for (int w2 = max(0, w1 - 2); w2 <= min(4, w1 + 2); w2++) {
            int p2 = h2 * 5 + w2;
            int base = (p1 * NP + p2) * (NDICT * 16) + og * 4;
            int d = ss[bl][p2], dp = ssp[bl][p2];
            float4 r1  = *(const float4*)&g_R1[base + d * 16];
            float4 r2a = *(const float4*)&g_R2[base + dp * 16];
            float4 r2b = *(const float4*)&g_R2[base + d * 16];
            a1.x += r1.x; a1.y += r1.y; a1.z += r1.z; a1.w += r1.w;
            a2.x += r2a.x - r2b.x; a2.y += r2a.y - r2b.y;
            a2.z += r2a.z - r2b.z; a2.w += r2a.w - r2b.w;
        }
    float4 o1 = make_float4(fmaxf(a1.x, 0.f), fmaxf(a1.y, 0.f),
                            fmaxf(a1.z, 0.f), fmaxf(a1.w, 0.f));
    float4 o2 = make_float4(fmaxf(a2.x, 0.f), fmaxf(a2.y, 0.f),
                            fmaxf(a2.z, 0.f), fmaxf(a2.w, 0.f));
    size_t off = (size_t)(b0 + bl) * K1 + p1 * 16 + og * 4;
    *(float4*)&g_A1[off] = o1;
    *(float4*)&g_A2[off] = o2;
}

// Stage 2: B800 = relu(conv2(A400) + b2). 8 batches/block, 200 threads.
#define CPAD 12
__global__ void __launch_bounds__(200) k_conv2(
    const float* __restrict__ A, const float* __restrict__ W2,
    const float* __restrict__ b2, float* __restrict__ Bo) {
    __shared__ float sA[16 * 7 * 7 * CPAD];
    __shared__ float sW[16 * 9 * 32];       // [o1*9+j][o2]
    int tid = threadIdx.x;
    int b0 = blockIdx.x * 8;

    for (int i = tid; i < 16 * 49 * CPAD; i += 200) sA[i] = 0.f;
    for (int i = tid; i < 4608; i += 200) {
        int o2 = i & 31, r = i >> 5;        // r = o1*9+j
        sW[i] = W2[o2 * 144 + r];
    }
    __syncthreads();
    for (int i = tid; i < 8 * K1; i += 200) {
        int b = i / K1, r = i % K1;
        int p = r >> 4, o1 = r & 15, h = p / 5, w = p % 5;
        sA[((o1 * 7 + h + 1) * 7 + (w + 1)) * CPAD + b] = A[(size_t)(b0 + b) * K1 + r];
    }
    __syncthreads();

    int pp = tid % 25, o2g = tid / 25;
    int hp = pp / 5, wp = pp % 5;
    float acc[4][8];
    #pragma unroll
    for (int q = 0; q < 4; q++)
        #pragma unroll
        for (int b = 0; b < 8; b++) acc[q][b] = 0.f;

    for (int o1 = 0; o1 < 16; o1++) {
        #pragma unroll
        for (int j = 0; j < 9; j++) {
            int kh = j / 3, kw = j % 3;
            float4 wv = *(const float4*)&sW[(o1 * 9 + j) * 32 + o2g * 4];
            int base = ((o1 * 7 + hp + kh) * 7 + (wp + kw)) * CPAD;
            float4 a0 = *(const float4*)&sA[base];
            float4 a1 = *(const float4*)&sA[base + 4];
            float a[8] = {a0.x, a0.y, a0.z, a0.w, a1.x, a1.y, a1.z, a1.w};
            float w[4] = {wv.x, wv.y, wv.z, wv.w};
            #pragma unroll
            for (int q = 0; q < 4; q++)
                #pragma unroll
                for (int b = 0; b < 8; b++) acc[q][b] += w[q] * a[b];
        }
    }

    #pragma unroll
    for (int q = 0; q < 4; q++) {
        int o2 = o2g * 4 + q;
        float bias = b2[o2];
        #pragma unroll
        for (int b = 0; b < 8; b++)
            Bo[(size_t)(b0 + b) * K2 + o2 * NP + pp] = fmaxf(acc[q][b] + bias, 0.f);
    }
}

// ---------------- 3xTF32 tensor-core NT GEMM ----------------
// C[M,N] = rowscale[m] * (A[M,K] . B[N,K]^T + bias[n])
// block tile 128x128, 8 warps (2x4) of 64x32, BK=16, double-buffered smem.
// smem layout [k][m] padded to 136 -> conflict-free fragment reads.
#define TBK 16
#define SPAD 136

__device__ __forceinline__ unsigned cvt_tf32(float x) {
    unsigned r;
    asm("cvt.rna.tf32.f32 %0, %1;" : "=r"(r) : "f"(x));
    return r;
}

__device__ __forceinline__ void mma8(float* d, const unsigned* a, const unsigned* b) {
    asm volatile(
        "mma.sync.aligned.m16n8k8.row.col.f32.tf32.tf32.f32 "
        "{%0,%1,%2,%3}, {%4,%5,%6,%7}, {%8,%9}, {%0,%1,%2,%3};"
        : "+f"(d[0]), "+f"(d[1]), "+f"(d[2]), "+f"(d[3])
        : "r"(a[0]), "r"(a[1]), "r"(a[2]), "r"(a[3]), "r"(b[0]), "r"(b[1]));
}

__global__ void __launch_bounds__(256) k_tgemm(
    const float* __restrict__ A, const float* __restrict__ B,
    const float* __restrict__ bias, const float* __restrict__ rowscale,
    float* __restrict__ C, int K, int N) {
    __shared__ float As[2][TBK][SPAD];
    __shared__ float Bs[2][TBK][SPAD];
    int tid = threadIdx.x;
    int wid = tid >> 5, lane = tid & 31;
    int g = lane >> 2, t4 = lane & 3;
    int wm = wid >> 2, wn = wid & 3;        // warp tile: rows 64*wm+, cols 32*wn+
    int bm = blockIdx.y * 128, bn = blockIdx.x * 128;

    int lrow = tid >> 1, lkh = (tid & 1) << 3;   // row 0..127, k-half 0/8
    const float* Ap = A + (size_t)(bm + lrow) * K + lkh;
    const float* Bp = B + (size_t)(bn + lrow) * K + lkh;

    float acc[4][4][4];
    #pragma unroll
    for (int mt = 0; mt < 4; mt++)
        #pragma unroll
        for (int nt = 0; nt < 4; nt++)
            #pragma unroll
            for (int q = 0; q < 4; q++) acc[mt][nt][q] = 0.f;

    // first slab
    {
        float4 a0 = *(const float4*)(Ap);
        float4 a1 = *(const float4*)(Ap + 4);
        float4 b0 = *(const float4*)(Bp);
        float4 b1 = *(const float4*)(Bp + 4);
        #pragma unroll
        for (int q = 0; q < 4; q++) {
            As[0][lkh + q][lrow]     = ((const float*)&a0)[q];
            As[0][lkh + 4 + q][lrow] = ((const float*)&a1)[q];
            Bs[0][lkh + q][lrow]     = ((const float*)&b0)[q];
            Bs[0][lkh + 4 + q][lrow] = ((const float*)&b1)[q];
        }
    }
    __syncthreads();

    int nT = K / TBK;
    int cur = 0;
    for (int t = 0; t < nT; t++) {
        float4 na0, na1, nb0, nb1;
        if (t + 1 < nT) {
            const float* Ap2 = Ap + (t + 1) * TBK;
            const float* Bp2 = Bp + (t + 1) * TBK;
            na0 = *(const float4*)(Ap2);
            na1 = *(const float4*)(Ap2 + 4);
            nb0 = *(const float4*)(Bp2);
            nb1 = *(const float4*)(Bp2 + 4);
        }
        #pragma unroll
        for (int ks = 0; ks < 2; ks++) {
            int kb = ks * 8;
            unsigned ahi[4][4], alo[4][4];
            #pragma unroll
            for (int mt = 0; mt < 4; mt++) {
                int mr = wm * 64 + mt * 16 + g;
                float v0 = As[cur][kb + t4][mr];
                float v1 = As[cur][kb + t4][mr + 8];
                float v2 = As[cur][kb + t4 + 4][mr];
                float v3 = As[cur][kb + t4 + 4][mr + 8];
                ahi[mt][0] = cvt_tf32(v0);
                ahi[mt][1] = cvt_tf32(v1);
                ahi[mt][2] = cvt_tf32(v2);
                ahi[mt][3] = cvt_tf32(v3);
                alo[mt][0] = cvt_tf32(v0 - __uint_as_float(ahi[mt][0]));
                alo[mt][1] = cvt_tf32(v1 - __uint_as_float(ahi[mt][1]));
                alo[mt][2] = cvt_tf32(v2 - __uint_as_float(ahi[mt][2]));
                alo[mt][3] = cvt_tf32(v3 - __uint_as_float(ahi[mt][3]));
            }
            unsigned bhi[4][2], blo[4][2];
            #pragma unroll
            for (int nt = 0; nt < 4; nt++) {
                int nc = wn * 32 + nt * 8 + g;
                float u0 = Bs[cur][kb + t4][nc];
                float u1 = Bs[cur][kb + t4 + 4][nc];
                bhi[nt][0] = cvt_tf32(u0);
                bhi[nt][1] = cvt_tf32(u1);
                blo[nt][0] = cvt_tf32(u0 - __uint_as_float(bhi[nt][0]));
                blo[nt][1] = cvt_tf32(u1 - __uint_as_float(bhi[nt][1]));
            }
            #pragma unroll
            for (int mt = 0; mt < 4; mt++)
                #pragma unroll
                for (int nt = 0; nt < 4; nt++) {
                    mma8(acc[mt][nt], ahi[mt], blo[nt]);
                    mma8(acc[mt][nt], alo[mt], bhi[nt]);
                    mma8(acc[mt][nt], ahi[mt], bhi[nt]);
                }
        }
        if (t + 1 < nT) {
            int nxt = cur ^ 1;
            #pragma unroll
            for (int q = 0; q < 4; q++) {
                As[nxt][lkh + q][lrow]     = ((const float*)&na0)[q];
                As[nxt][lkh + 4 + q][lrow] = ((const float*)&na1)[q];
                Bs[nxt][lkh + q][lrow]     = ((const float*)&nb0)[q];
                Bs[nxt][lkh + 4 + q][lrow] = ((const float*)&nb1)[q];
            }
            __syncthreads();
            cur = nxt;
        }
    }

    // epilogue
    #pragma unroll
    for (int mt = 0; mt < 4; mt++) {
        int r0 = bm + wm * 64 + mt * 16 + g;
        float rs0 = rowscale ? rowscale[r0] : 1.f;
        float rs1 = rowscale ? rowscale[r0 + 8] : 1.f;
        #pragma unroll
        for (int nt = 0; nt < 4; nt++) {
            int c0 = bn + wn * 32 + nt * 8 + 2 * t4;
            float bv0 = bias ? bias[c0] : 0.f;
            float bv1 = bias ? bias[c0 + 1] : 0.f;
            float2 w0, w1;
            w0.x = (acc[mt][nt][0] + bv0) * rs0;
            w0.y = (acc[mt][nt][1] + bv1) * rs0;
            w1.x = (acc[mt][nt][2] + bv0) * rs1;
            w1.y = (acc[mt][nt][3] + bv1) * rs1;
            *(float2*)&C[(size_t)r0 * N + c0] = w0;
            *(float2*)&C[(size_t)(r0 + 8) * N + c0] = w1;
        }
    }
}

// coef[i] = exp(scale) / (||U1_i|| + 1e-4)
__global__ void k_coef(const float* __restrict__ scale) {
    int i = blockIdx.x * 8 + (threadIdx.x >> 5);
    int lane = threadIdx.x & 31;
    const float* u = g_U1 + (size_t)i * NE;
    float s = 0.f;
    #pragma unroll
    for (int k = 0; k < 8; k++) { float v = u[lane + 32 * k]; s += v * v; }
    #pragma unroll
    for (int o = 16; o; o >>= 1) s += __shfl_xor_sync(0xffffffffu, s, o);
    if (lane == 0) g_coef[i] = expf(scale[0]) / (sqrtf(s) + 1e-4f);
}

// argmax over 512 scores per row, first-occurrence tie-break.
__global__ void k_argmax() {
    int i = blockIdx.x * 8 + (threadIdx.x >> 5);
    int lane = threadIdx.x & 31;
    const float* r = g_scores + (size_t)i * NNZ;
    float best = -FLT_MAX; int bi = 0;
    for (int z = lane; z < NNZ; z += 32) {
        float v = r[z];
        if (v > best) { best = v; bi = z; }
    }
    #pragma unroll
    for (int off = 16; off; off >>= 1) {
        float ov = __shfl_down_sync(0xffffffffu, best, off);
        int   oi = __shfl_down_sync(0xffffffffu, bi, off);
        if (ov > best || (ov == best && oi < bi)) { best = ov; bi = oi; }
    }
    if (lane == 0) g_zind[i] = bi;
}

// out[i][j] = G[i][zind[j]]  (256 MB coalesced write)
__global__ void k_out(float* __restrict__ out) {
    __shared__ float row[NNZ];
    __shared__ int zj[4096];
    int i = blockIdx.y;
    int jb = blockIdx.x * 4096;
    for (int t = threadIdx.x; t < NNZ; t += 256) row[t] = g_G[(size_t)i * NNZ + t];
    for (int t = threadIdx.x; t < 4096; t += 256) zj[t] = g_zind[jb + t];
    __syncthreads();
    float* op = out + (size_t)i * BATCH + jb;
    #pragma unroll
    for (int k = 0; k < 16; k++) {
        int j = k * 256 + threadIdx.x;
        op[j] = row[zj[j]];
    }
}

// ---------------- launcher ----------------
extern "C" void kernel_launch(void* const* d_in, const int* in_sizes, int n_in,
                              void* d_out, int out_size) {
    const int*   s     = (const int*)d_in[0];
    const int*   sp    = (const int*)d_in[1];
    const float* tab   = (const float*)d_in[2];
    const float* cw    = (const float*)d_in[3];
    const float* cb    = (const float*)d_in[4];
    const float* w1a   = (const float*)d_in[5];
    const float* b1a   = (const float*)d_in[6];
    const float* w2a   = (const float*)d_in[7];
    const float* b2a   = (const float*)d_in[8];
    const float* lwa   = (const float*)d_in[9];
    const float* lba   = (const float*)d_in[10];
    const float* w1b   = (const float*)d_in[11];
    const float* b1b   = (const float*)d_in[12];
    const float* w2b   = (const float*)d_in[13];
    const float* b2b   = (const float*)d_in[14];
    const float* lwb   = (const float*)d_in[15];
    const float* lbb   = (const float*)d_in[16];
    const float* zv    = (const float*)d_in[17];
    const float* scale = (const float*)d_in[18];
    float* out = (float*)d_out;

    float *pR1, *pR2, *pA1, *pA2, *pB1, *pB2, *pU1, *pE2, *pzn,
          *pscores, *pG, *pcoef;
    cudaGetSymbolAddress((void**)&pR1, g_R1);
    cudaGetSymbolAddress((void**)&pR2, g_R2);
    cudaGetSymbolAddress((void**)&pA1, g_A1);
    cudaGetSymbolAddress((void**)&pA2, g_A2);
    cudaGetSymbolAddress((void**)&pB1, g_B1);
    cudaGetSymbolAddress((void**)&pB2, g_B2);
    cudaGetSymbolAddress((void**)&pU1, g_U1);
    cudaGetSymbolAddress((void**)&pE2, g_E2);
    cudaGetSymbolAddress((void**)&pzn, g_zn);
    cudaGetSymbolAddress((void**)&pscores, g_scores);
    cudaGetSymbolAddress((void**)&pG, g_G);
    cudaGetSymbolAddress((void**)&pcoef, g_coef);

    // Precompute (every call; deterministic)
    k_embn<<<1, 448>>>(tab);
    k_zn<<<64, 256>>>(zv);
    k_PE<<<32, 256>>>(cw);
    k_R<<<NP * NDICT, 400>>>(w1a, pR1);
    k_R<<<NP * NDICT, 400>>>(w1b, pR2);
    k_C1<<<2, 256>>>(w1a, b1a, cb);

    // Main pipeline
    k_stage1<<<BATCH / 8, 800>>>(s, sp, b1b);

    k_conv2<<<BATCH / 8, 200>>>(pA1, w2a, b2a, pB1);
    k_conv2<<<BATCH / 8, 200>>>(pA2, w2b, b2b, pB2);

    dim3 gU(NE / 128, BATCH / 128);      // 2 x 64
    k_tgemm<<<gU, 256>>>(pB1, lwa, lba, nullptr, pU1, K2, NE);
    k_coef<<<1024, 256>>>(scale);

    // embed2 (with lb2 folded in), then scores = E2 . zn^T
    k_tgemm<<<gU, 256>>>(pB2, lwb, lbb, nullptr, pE2, K2, NE);
    dim3 gZ(NNZ / 128, BATCH / 128);     // 4 x 64
    k_tgemm<<<gZ, 256>>>(pE2, pzn, nullptr, nullptr, pscores, NE, NNZ);
    k_argmax<<<1024, 256>>>();

    k_tgemm<<<gZ, 256>>>(pU1, pzn, nullptr, pcoef, pG, NE, NNZ);

    k_out<<<dim3(2, BATCH), 256>>>(out);
}